// round 4
// baseline (speedup 1.0000x reference)
#include <cuda_runtime.h>
#include <cstdint>

#define F 128
#define M 2
#define ROW 1024              // STRIDE*F*M floats per output row
#define NWIN 4                // output windows (~64MB each, fits 126MB L2)
#define CAP (1u << 21)        // per-window bucket capacity (2M; E/4=1M expected)
#define SCAT_BLOCKS 592       // 4 blocks/SM * 148 SMs -> single wave

// Scratch: 4 windows x 2M events x 8B = 67MB (static device array, allowed)
__device__ uint2    g_buf[NWIN * CAP];
__device__ unsigned g_cnt[NWIN];

// ---------------------------------------------------------------------------
__global__ void init_counters_kernel() {
    if (threadIdx.x < NWIN) g_cnt[threadIdx.x] = 0;
}

// ---------------------------------------------------------------------------
// Zero one window; stores allocate dirty in L2 and stay resident for the
// matching scatter pass.
// ---------------------------------------------------------------------------
__global__ void __launch_bounds__(256) zero_win_kernel(float4* __restrict__ out4,
                                                       long long n4) {
    long long i = (long long)blockIdx.x * blockDim.x + threadIdx.x;
    if (i < n4) out4[i] = make_float4(0.f, 0.f, 0.f, 0.f);
}

// ---------------------------------------------------------------------------
// Bucketize: single streaming pass. Event -> (offset = seg*1024 + id*2, dt)
// appended to its window's bucket. Block-local shared counting, one global
// atomicAdd per window per block.
// ---------------------------------------------------------------------------
__global__ void __launch_bounds__(256) bucket_kernel(
    const float4* __restrict__ dt4,
    const int4*   __restrict__ id4,
    const int4*   __restrict__ seg4,
    int n4,
    const float* __restrict__ dt_s,
    const int*   __restrict__ id_s,
    const int*   __restrict__ seg_s,
    int n_events,
    int segs_per_win)
{
    __shared__ unsigned s_cnt[NWIN];
    __shared__ unsigned s_base[NWIN];
    int t = threadIdx.x;
    if (t < NWIN) s_cnt[t] = 0;
    __syncthreads();

    int i = blockIdx.x * blockDim.x + t;

    int      w[5];
    unsigned pos[5];
    uint2    pay[5];
    int      nev = 0;

    if (i < n4) {
        float4 d  = __ldcs(&dt4[i]);
        int4   id = __ldcs(&id4[i]);
        int4   sg = __ldcs(&seg4[i]);
        float dts[4] = {d.x, d.y, d.z, d.w};
        int   ids[4] = {id.x, id.y, id.z, id.w};
        int   sgs[4] = {sg.x, sg.y, sg.z, sg.w};
        #pragma unroll
        for (int k = 0; k < 4; k++) {
            unsigned off = (unsigned)sgs[k] * ROW + (unsigned)ids[k] * M;
            int ww = sgs[k] / segs_per_win;
            w[nev]   = ww;
            pay[nev] = make_uint2(off, __float_as_uint(dts[k]));
            pos[nev] = atomicAdd(&s_cnt[ww], 1u);
            nev++;
        }
    }
    int rem = n_events & 3;
    if (blockIdx.x == 0 && t < rem) {
        int e = n4 * 4 + t;
        unsigned off = (unsigned)seg_s[e] * ROW + (unsigned)id_s[e] * M;
        int ww = seg_s[e] / segs_per_win;
        w[nev]   = ww;
        pay[nev] = make_uint2(off, __float_as_uint(dt_s[e]));
        pos[nev] = atomicAdd(&s_cnt[ww], 1u);
        nev++;
    }
    __syncthreads();

    if (t < NWIN) s_base[t] = atomicAdd(&g_cnt[t], s_cnt[t]);
    __syncthreads();

    for (int k = 0; k < nev; k++) {
        unsigned idx = s_base[w[k]] + pos[k];
        if (idx < CAP)
            __stcs(&g_buf[(unsigned)w[k] * CAP + idx], pay[k]);
    }
}

// ---------------------------------------------------------------------------
// Scatter one window's bucket. Single-wave grid-stride, 4 events (2x uint4,
// both loads issued before any use) per thread per iteration. Targets are
// L2-resident (just zeroed) so red.global.add.v2.f32 is an L2-hit RMW.
// ---------------------------------------------------------------------------
__device__ __forceinline__ void fire_event(unsigned off, unsigned dt_bits,
                                           const float2* rate2,
                                           float* __restrict__ out) {
    float  dtv = __uint_as_float(dt_bits);
    float2 r   = rate2[(off >> 1) & (F - 1)];
    float v0 = __expf(-r.x * dtv);
    float v1 = __expf(-r.y * dtv);
    asm volatile("red.global.add.v2.f32 [%0], {%1, %2};"
                 :: "l"(out + off), "f"(v0), "f"(v1) : "memory");
}

__global__ void __launch_bounds__(256) scatter_bucket_kernel(
    const float* __restrict__ decay,   // [F*M]
    float* __restrict__ out,
    int w)
{
    __shared__ float2 rate2[F];
    int t = threadIdx.x;
    if (t < F) {
        float x0 = decay[t * M + 0];
        float x1 = decay[t * M + 1];
        rate2[t].x = fmaxf(x0, 0.f) + log1pf(expf(-fabsf(x0)));
        rate2[t].y = fmaxf(x1, 0.f) + log1pf(expf(-fabsf(x1)));
    }
    __syncthreads();

    unsigned cnt = g_cnt[w];
    if (cnt > CAP) cnt = CAP;
    const uint2* buf = g_buf + (size_t)w * CAP;

    unsigned stride = (unsigned)gridDim.x * blockDim.x * 4u;
    unsigned e      = ((unsigned)blockIdx.x * blockDim.x + t) * 4u;

    // full groups of 4
    for (; e + 3 < cnt; e += stride) {
        uint4 qa = __ldcs((const uint4*)&buf[e]);
        uint4 qb = __ldcs((const uint4*)&buf[e + 2]);
        fire_event(qa.x, qa.y, rate2, out);
        fire_event(qa.z, qa.w, rate2, out);
        fire_event(qb.x, qb.y, rate2, out);
        fire_event(qb.z, qb.w, rate2, out);
    }
    // tail (at most one partial group per thread)
    for (; e < cnt; e++) {
        uint2 q = __ldcs(&buf[e]);
        fire_event(q.x, q.y, rate2, out);
    }
}

// ---------------------------------------------------------------------------
// metadata order: 0=dt[E] f32, 1=times_out (unused), 2=decay_rate[256] f32,
//                 3=successor_kernel_channel_ids[E] i32, 4=segment_ids_out[E] i32
// output: f32[n_out*1024]
// ---------------------------------------------------------------------------
extern "C" void kernel_launch(void* const* d_in, const int* in_sizes, int n_in,
                              void* d_out, int out_size) {
    const float* dt    = (const float*)d_in[0];
    const float* decay = (const float*)d_in[2];
    const int*   ids   = (const int*)d_in[3];
    const int*   segs  = (const int*)d_in[4];
    float*       out   = (float*)d_out;

    int E  = in_sizes[0];
    int n4 = E >> 2;

    long long n_out = (long long)out_size / ROW;
    int segs_per_win = (int)((n_out + NWIN - 1) / NWIN);

    init_counters_kernel<<<1, 32>>>();

    int bblocks = (n4 + 255) / 256;
    if (bblocks < 1) bblocks = 1;
    bucket_kernel<<<bblocks, 256>>>(
        (const float4*)dt, (const int4*)ids, (const int4*)segs,
        n4, dt, ids, segs, E, segs_per_win);

    for (int w = 0; w < NWIN; w++) {
        long long seg_lo = (long long)w * segs_per_win;
        if (seg_lo >= n_out) break;
        long long seg_hi = seg_lo + segs_per_win;
        if (seg_hi > n_out) seg_hi = n_out;

        long long base_f = seg_lo * ROW;
        long long n4z    = ((seg_hi - seg_lo) * ROW) >> 2;
        long long zb     = (n4z + 255) / 256;
        zero_win_kernel<<<(unsigned)zb, 256>>>((float4*)(out + base_f), n4z);

        scatter_bucket_kernel<<<SCAT_BLOCKS, 256>>>(decay, out, w);
    }
}